// round 11
// baseline (speedup 1.0000x reference)
#include <cuda_runtime.h>

#define NRES 1024
#define CM   256
#define CZ   128
#define EPSF 1e-5f
#define NROWS (NRES * NRES)
#define ZBLOCKS (NROWS / 64)      // 16384
#define MBLOCKS (NRES / 16)       // 64 (16 warps/block, 1 row/warp)

// Fused distogram table: T[b][c] = lin_b[c] + ln_z_b[c] + (b<15 ? lin_w[c,b] : 0)
// bin 15 == "no bin active" row (bias-only).
__device__ float g_T[16 * CZ];

__device__ __forceinline__ int dist_bin(float d2)
{
    // count of sq_bins strictly below d2 (exact fp32 boundary semantics:
    // 3.25 + 1.25k is exactly representable; squared in fp32 like the ref)
    int nb = 0;
    #pragma unroll
    for (int k = 0; k < 15; k++) {
        float bb = 3.25f + 1.25f * (float)k;
        bb = bb * bb;
        nb += (d2 > bb) ? 1 : 0;
    }
    int bin = 15;                 // no bin active -> bias-only row
    if (nb > 0) {
        if (nb == 15) {
            bin = 14;             // upper = INF
        } else {
            float bb = 3.25f + 1.25f * (float)nb;
            bb = bb * bb;
            if (d2 < bb) bin = nb - 1;   // strict: equality -> no bin
        }
    }
    return bin;
}

// ---------------------------------------------------------------------------
// Prep kernel: build g_T only (8 blocks x 256 threads).
// ---------------------------------------------------------------------------
__global__ void re_prep_kernel(
    const float* __restrict__ lin_w,
    const float* __restrict__ lin_b,
    const float* __restrict__ ln_z_b)
{
    int idx = blockIdx.x * 256 + threadIdx.x;   // 0..2047
    int b = idx >> 7;
    int c = idx & (CZ - 1);
    float v = lin_b[c] + ln_z_b[c];
    if (b < 15) v += lin_w[c * 15 + b];
    g_T[idx] = v;
}

// ---------------------------------------------------------------------------
// Main kernel.
//   blocks 0..ZBLOCKS-1          : z path, one warp per 4 consecutive rows
//   blocks ZBLOCKS..ZBLOCKS+63   : m layernorm, one warp per row of 256
// z path: bins computed warp-locally (one dist_bin chain per lane, lane&3
// selects the row) then shuffle-broadcast; all wide loads front-batched.
//   out_z = (z-mu)*rs*w[c] + T[bin][c]
// ---------------------------------------------------------------------------
__global__ __launch_bounds__(512) void re_main_kernel(
    const float4* __restrict__ z4,
    const float*  __restrict__ x,
    const float4* __restrict__ w4,      // ln_z_w as float4[32]
    float4*       __restrict__ out4,    // z output
    const float4* __restrict__ m4,
    const float4* __restrict__ mw4,     // ln_m_w
    const float4* __restrict__ mb4,     // ln_m_b
    float4*       __restrict__ outm4)   // m output
{
    int tid  = threadIdx.x;
    int lane = tid & 31;

    if (blockIdx.x >= ZBLOCKS) {
        // ---------------- m layernorm path ----------------
        int row = (blockIdx.x - ZBLOCKS) * 16 + (tid >> 5);  // 0..1023

        const float4* r = m4 + (size_t)row * 64;
        float4 a = r[lane];
        float4 c = r[lane + 32];

        float s1 = a.x + a.y + a.z + a.w + c.x + c.y + c.z + c.w;
        float s2 = a.x * a.x + a.y * a.y + a.z * a.z + a.w * a.w
                 + c.x * c.x + c.y * c.y + c.z * c.z + c.w * c.w;
        #pragma unroll
        for (int o = 16; o; o >>= 1) {
            s1 += __shfl_xor_sync(0xffffffffu, s1, o);
            s2 += __shfl_xor_sync(0xffffffffu, s2, o);
        }
        float mu  = s1 * (1.0f / CM);
        float var = s2 * (1.0f / CM) - mu * mu;
        float rs  = rsqrtf(var + EPSF);

        float4 wa = mw4[lane],      ba = mb4[lane];
        float4 wc = mw4[lane + 32], bc = mb4[lane + 32];

        float4 oa, oc;
        oa.x = (a.x - mu) * rs * wa.x + ba.x;  oa.y = (a.y - mu) * rs * wa.y + ba.y;
        oa.z = (a.z - mu) * rs * wa.z + ba.z;  oa.w = (a.w - mu) * rs * wa.w + ba.w;
        oc.x = (c.x - mu) * rs * wc.x + bc.x;  oc.y = (c.y - mu) * rs * wc.y + bc.y;
        oc.z = (c.z - mu) * rs * wc.z + bc.z;  oc.w = (c.w - mu) * rs * wc.w + bc.w;

        outm4[(size_t)row * 64 + lane]      = oa;
        outm4[(size_t)row * 64 + lane + 32] = oc;
        return;
    }

    // ---------------- z path ----------------
    int r0 = blockIdx.x * 64 + (tid >> 5) * 4;   // rows r0..r0+3, same i

    // warp-local bin computation (transient registers)
    int myrow = r0 + (lane & 3);
    int i = myrow >> 10;
    int j = myrow & (NRES - 1);
    float p0 = __ldg(&x[3 * i + 0]) - __ldg(&x[3 * j + 0]);
    float p1 = __ldg(&x[3 * i + 1]) - __ldg(&x[3 * j + 1]);
    float p2 = __ldg(&x[3 * i + 2]) - __ldg(&x[3 * j + 2]);
    int mybin = dist_bin(p0 * p0 + p1 * p1 + p2 * p2);
    int bin0 = __shfl_sync(0xffffffffu, mybin, 0);
    int bin1 = __shfl_sync(0xffffffffu, mybin, 1);
    int bin2 = __shfl_sync(0xffffffffu, mybin, 2);
    int bin3 = __shfl_sync(0xffffffffu, mybin, 3);

    // front-batch ALL wide loads
    const float4* zp = z4 + (size_t)r0 * 32 + lane;
    float4 v0 = zp[0];
    float4 v1 = zp[32];
    float4 v2 = zp[64];
    float4 v3 = zp[96];
    const float4* T4 = reinterpret_cast<const float4*>(g_T);
    float4 t0 = __ldg(T4 + bin0 * 32 + lane);   // uniform per warp, L1 hit
    float4 t1 = __ldg(T4 + bin1 * 32 + lane);
    float4 t2 = __ldg(T4 + bin2 * 32 + lane);
    float4 t3 = __ldg(T4 + bin3 * 32 + lane);
    float4 w  = __ldg(w4 + lane);               // same line all warps, L1 hit

    // interleaved one-pass moments for four rows
    float a1 = v0.x + v0.y + v0.z + v0.w;
    float a2 = v0.x * v0.x + v0.y * v0.y + v0.z * v0.z + v0.w * v0.w;
    float b1 = v1.x + v1.y + v1.z + v1.w;
    float b2 = v1.x * v1.x + v1.y * v1.y + v1.z * v1.z + v1.w * v1.w;
    float c1 = v2.x + v2.y + v2.z + v2.w;
    float c2 = v2.x * v2.x + v2.y * v2.y + v2.z * v2.z + v2.w * v2.w;
    float d1 = v3.x + v3.y + v3.z + v3.w;
    float d2 = v3.x * v3.x + v3.y * v3.y + v3.z * v3.z + v3.w * v3.w;
    #pragma unroll
    for (int o = 16; o; o >>= 1) {
        a1 += __shfl_xor_sync(0xffffffffu, a1, o);
        a2 += __shfl_xor_sync(0xffffffffu, a2, o);
        b1 += __shfl_xor_sync(0xffffffffu, b1, o);
        b2 += __shfl_xor_sync(0xffffffffu, b2, o);
        c1 += __shfl_xor_sync(0xffffffffu, c1, o);
        c2 += __shfl_xor_sync(0xffffffffu, c2, o);
        d1 += __shfl_xor_sync(0xffffffffu, d1, o);
        d2 += __shfl_xor_sync(0xffffffffu, d2, o);
    }
    float mu0 = a1 * (1.0f / CZ);
    float rs0 = rsqrtf(a2 * (1.0f / CZ) - mu0 * mu0 + EPSF);
    float mu1 = b1 * (1.0f / CZ);
    float rs1 = rsqrtf(b2 * (1.0f / CZ) - mu1 * mu1 + EPSF);
    float mu2 = c1 * (1.0f / CZ);
    float rs2 = rsqrtf(c2 * (1.0f / CZ) - mu2 * mu2 + EPSF);
    float mu3 = d1 * (1.0f / CZ);
    float rs3 = rsqrtf(d2 * (1.0f / CZ) - mu3 * mu3 + EPSF);

    float4* op = out4 + (size_t)r0 * 32 + lane;
    float4 o;
    float k0, k1, k2, k3;

    k0 = rs0 * w.x; k1 = rs0 * w.y; k2 = rs0 * w.z; k3 = rs0 * w.w;
    o.x = (v0.x - mu0) * k0 + t0.x;  o.y = (v0.y - mu0) * k1 + t0.y;
    o.z = (v0.z - mu0) * k2 + t0.z;  o.w = (v0.w - mu0) * k3 + t0.w;
    op[0] = o;

    k0 = rs1 * w.x; k1 = rs1 * w.y; k2 = rs1 * w.z; k3 = rs1 * w.w;
    o.x = (v1.x - mu1) * k0 + t1.x;  o.y = (v1.y - mu1) * k1 + t1.y;
    o.z = (v1.z - mu1) * k2 + t1.z;  o.w = (v1.w - mu1) * k3 + t1.w;
    op[32] = o;

    k0 = rs2 * w.x; k1 = rs2 * w.y; k2 = rs2 * w.z; k3 = rs2 * w.w;
    o.x = (v2.x - mu2) * k0 + t2.x;  o.y = (v2.y - mu2) * k1 + t2.y;
    o.z = (v2.z - mu2) * k2 + t2.z;  o.w = (v2.w - mu2) * k3 + t2.w;
    op[64] = o;

    k0 = rs3 * w.x; k1 = rs3 * w.y; k2 = rs3 * w.z; k3 = rs3 * w.w;
    o.x = (v3.x - mu3) * k0 + t3.x;  o.y = (v3.y - mu3) * k1 + t3.y;
    o.z = (v3.z - mu3) * k2 + t3.z;  o.w = (v3.w - mu3) * k3 + t3.w;
    op[96] = o;
}

extern "C" void kernel_launch(void* const* d_in, const int* in_sizes, int n_in,
                              void* d_out, int out_size)
{
    const float* m      = (const float*)d_in[0];
    const float* z      = (const float*)d_in[1];
    const float* x      = (const float*)d_in[2];
    const float* ln_m_w = (const float*)d_in[3];
    const float* ln_m_b = (const float*)d_in[4];
    const float* ln_z_w = (const float*)d_in[5];
    const float* ln_z_b = (const float*)d_in[6];
    const float* lin_w  = (const float*)d_in[7];
    const float* lin_b  = (const float*)d_in[8];

    float* out_m = (float*)d_out;                      // [1024, 256]
    float* out_z = out_m + (size_t)NRES * CM;          // [1024, 1024, 128]

    // tiny prep: build g_T (8 blocks)
    re_prep_kernel<<<8, 256>>>(lin_w, lin_b, ln_z_b);

    // main: z (blocks 0..16383) + m layernorm (blocks 16384..16447)
    re_main_kernel<<<ZBLOCKS + MBLOCKS, 512>>>(
        (const float4*)z, x, (const float4*)ln_z_w, (float4*)out_z,
        (const float4*)m, (const float4*)ln_m_w, (const float4*)ln_m_b,
        (float4*)out_m);
}

// round 12
// speedup vs baseline: 1.0004x; 1.0004x over previous
#include <cuda_runtime.h>

#define NRES 1024
#define CM   256
#define CZ   128
#define EPSF 1e-5f
#define NROWS (NRES * NRES)
#define ZBLOCKS (NROWS / 64)      // 16384
#define MBLOCKS (NRES / 16)       // 64 (16 warps/block, 1 row/warp)

// Fused distogram table: T[b][c] = lin_b[c] + ln_z_b[c] + (b<15 ? lin_w[c,b] : 0)
// bin 15 == "no bin active" row (bias-only).
__device__ float g_T[16 * CZ];

__device__ __forceinline__ int dist_bin(float d2)
{
    // count of sq_bins strictly below d2 (exact fp32 boundary semantics:
    // 3.25 + 1.25k is exactly representable; squared in fp32 like the ref)
    int nb = 0;
    #pragma unroll
    for (int k = 0; k < 15; k++) {
        float bb = 3.25f + 1.25f * (float)k;
        bb = bb * bb;
        nb += (d2 > bb) ? 1 : 0;
    }
    int bin = 15;                 // no bin active -> bias-only row
    if (nb > 0) {
        if (nb == 15) {
            bin = 14;             // upper = INF
        } else {
            float bb = 3.25f + 1.25f * (float)nb;
            bb = bb * bb;
            if (d2 < bb) bin = nb - 1;   // strict: equality -> no bin
        }
    }
    return bin;
}

// ---------------------------------------------------------------------------
// Prep kernel: build g_T only (8 blocks x 256 threads).
// ---------------------------------------------------------------------------
__global__ void re_prep_kernel(
    const float* __restrict__ lin_w,
    const float* __restrict__ lin_b,
    const float* __restrict__ ln_z_b)
{
    int idx = blockIdx.x * 256 + threadIdx.x;   // 0..2047
    int b = idx >> 7;
    int c = idx & (CZ - 1);
    float v = lin_b[c] + ln_z_b[c];
    if (b < 15) v += lin_w[c * 15 + b];
    g_T[idx] = v;
}

// ---------------------------------------------------------------------------
// Main kernel.
//   blocks 0..ZBLOCKS-1          : z path, one warp per 4 consecutive rows
//   blocks ZBLOCKS..ZBLOCKS+63   : m layernorm, one warp per row of 256
// z path: bins computed warp-locally (one dist_bin chain per lane, lane&3
// selects the row) then shuffle-broadcast; all wide loads front-batched.
//   out_z = (z-mu)*rs*w[c] + T[bin][c]
// ---------------------------------------------------------------------------
__global__ __launch_bounds__(512) void re_main_kernel(
    const float4* __restrict__ z4,
    const float*  __restrict__ x,
    const float4* __restrict__ w4,      // ln_z_w as float4[32]
    float4*       __restrict__ out4,    // z output
    const float4* __restrict__ m4,
    const float4* __restrict__ mw4,     // ln_m_w
    const float4* __restrict__ mb4,     // ln_m_b
    float4*       __restrict__ outm4)   // m output
{
    int tid  = threadIdx.x;
    int lane = tid & 31;

    if (blockIdx.x >= ZBLOCKS) {
        // ---------------- m layernorm path ----------------
        int row = (blockIdx.x - ZBLOCKS) * 16 + (tid >> 5);  // 0..1023

        const float4* r = m4 + (size_t)row * 64;
        float4 a = r[lane];
        float4 c = r[lane + 32];

        float s1 = a.x + a.y + a.z + a.w + c.x + c.y + c.z + c.w;
        float s2 = a.x * a.x + a.y * a.y + a.z * a.z + a.w * a.w
                 + c.x * c.x + c.y * c.y + c.z * c.z + c.w * c.w;
        #pragma unroll
        for (int o = 16; o; o >>= 1) {
            s1 += __shfl_xor_sync(0xffffffffu, s1, o);
            s2 += __shfl_xor_sync(0xffffffffu, s2, o);
        }
        float mu  = s1 * (1.0f / CM);
        float var = s2 * (1.0f / CM) - mu * mu;
        float rs  = rsqrtf(var + EPSF);

        float4 wa = mw4[lane],      ba = mb4[lane];
        float4 wc = mw4[lane + 32], bc = mb4[lane + 32];

        float4 oa, oc;
        oa.x = (a.x - mu) * rs * wa.x + ba.x;  oa.y = (a.y - mu) * rs * wa.y + ba.y;
        oa.z = (a.z - mu) * rs * wa.z + ba.z;  oa.w = (a.w - mu) * rs * wa.w + ba.w;
        oc.x = (c.x - mu) * rs * wc.x + bc.x;  oc.y = (c.y - mu) * rs * wc.y + bc.y;
        oc.z = (c.z - mu) * rs * wc.z + bc.z;  oc.w = (c.w - mu) * rs * wc.w + bc.w;

        outm4[(size_t)row * 64 + lane]      = oa;
        outm4[(size_t)row * 64 + lane + 32] = oc;
        return;
    }

    // ---------------- z path ----------------
    int r0 = blockIdx.x * 64 + (tid >> 5) * 4;   // rows r0..r0+3, same i

    // warp-local bin computation (transient registers)
    int myrow = r0 + (lane & 3);
    int i = myrow >> 10;
    int j = myrow & (NRES - 1);
    float p0 = __ldg(&x[3 * i + 0]) - __ldg(&x[3 * j + 0]);
    float p1 = __ldg(&x[3 * i + 1]) - __ldg(&x[3 * j + 1]);
    float p2 = __ldg(&x[3 * i + 2]) - __ldg(&x[3 * j + 2]);
    int mybin = dist_bin(p0 * p0 + p1 * p1 + p2 * p2);
    int bin0 = __shfl_sync(0xffffffffu, mybin, 0);
    int bin1 = __shfl_sync(0xffffffffu, mybin, 1);
    int bin2 = __shfl_sync(0xffffffffu, mybin, 2);
    int bin3 = __shfl_sync(0xffffffffu, mybin, 3);

    // front-batch ALL wide loads
    const float4* zp = z4 + (size_t)r0 * 32 + lane;
    float4 v0 = zp[0];
    float4 v1 = zp[32];
    float4 v2 = zp[64];
    float4 v3 = zp[96];
    const float4* T4 = reinterpret_cast<const float4*>(g_T);
    float4 t0 = __ldg(T4 + bin0 * 32 + lane);   // uniform per warp, L1 hit
    float4 t1 = __ldg(T4 + bin1 * 32 + lane);
    float4 t2 = __ldg(T4 + bin2 * 32 + lane);
    float4 t3 = __ldg(T4 + bin3 * 32 + lane);
    float4 w  = __ldg(w4 + lane);               // same line all warps, L1 hit

    // interleaved one-pass moments for four rows
    float a1 = v0.x + v0.y + v0.z + v0.w;
    float a2 = v0.x * v0.x + v0.y * v0.y + v0.z * v0.z + v0.w * v0.w;
    float b1 = v1.x + v1.y + v1.z + v1.w;
    float b2 = v1.x * v1.x + v1.y * v1.y + v1.z * v1.z + v1.w * v1.w;
    float c1 = v2.x + v2.y + v2.z + v2.w;
    float c2 = v2.x * v2.x + v2.y * v2.y + v2.z * v2.z + v2.w * v2.w;
    float d1 = v3.x + v3.y + v3.z + v3.w;
    float d2 = v3.x * v3.x + v3.y * v3.y + v3.z * v3.z + v3.w * v3.w;
    #pragma unroll
    for (int o = 16; o; o >>= 1) {
        a1 += __shfl_xor_sync(0xffffffffu, a1, o);
        a2 += __shfl_xor_sync(0xffffffffu, a2, o);
        b1 += __shfl_xor_sync(0xffffffffu, b1, o);
        b2 += __shfl_xor_sync(0xffffffffu, b2, o);
        c1 += __shfl_xor_sync(0xffffffffu, c1, o);
        c2 += __shfl_xor_sync(0xffffffffu, c2, o);
        d1 += __shfl_xor_sync(0xffffffffu, d1, o);
        d2 += __shfl_xor_sync(0xffffffffu, d2, o);
    }
    float mu0 = a1 * (1.0f / CZ);
    float rs0 = rsqrtf(a2 * (1.0f / CZ) - mu0 * mu0 + EPSF);
    float mu1 = b1 * (1.0f / CZ);
    float rs1 = rsqrtf(b2 * (1.0f / CZ) - mu1 * mu1 + EPSF);
    float mu2 = c1 * (1.0f / CZ);
    float rs2 = rsqrtf(c2 * (1.0f / CZ) - mu2 * mu2 + EPSF);
    float mu3 = d1 * (1.0f / CZ);
    float rs3 = rsqrtf(d2 * (1.0f / CZ) - mu3 * mu3 + EPSF);

    float4* op = out4 + (size_t)r0 * 32 + lane;
    float4 o;
    float k0, k1, k2, k3;

    k0 = rs0 * w.x; k1 = rs0 * w.y; k2 = rs0 * w.z; k3 = rs0 * w.w;
    o.x = (v0.x - mu0) * k0 + t0.x;  o.y = (v0.y - mu0) * k1 + t0.y;
    o.z = (v0.z - mu0) * k2 + t0.z;  o.w = (v0.w - mu0) * k3 + t0.w;
    op[0] = o;

    k0 = rs1 * w.x; k1 = rs1 * w.y; k2 = rs1 * w.z; k3 = rs1 * w.w;
    o.x = (v1.x - mu1) * k0 + t1.x;  o.y = (v1.y - mu1) * k1 + t1.y;
    o.z = (v1.z - mu1) * k2 + t1.z;  o.w = (v1.w - mu1) * k3 + t1.w;
    op[32] = o;

    k0 = rs2 * w.x; k1 = rs2 * w.y; k2 = rs2 * w.z; k3 = rs2 * w.w;
    o.x = (v2.x - mu2) * k0 + t2.x;  o.y = (v2.y - mu2) * k1 + t2.y;
    o.z = (v2.z - mu2) * k2 + t2.z;  o.w = (v2.w - mu2) * k3 + t2.w;
    op[64] = o;

    k0 = rs3 * w.x; k1 = rs3 * w.y; k2 = rs3 * w.z; k3 = rs3 * w.w;
    o.x = (v3.x - mu3) * k0 + t3.x;  o.y = (v3.y - mu3) * k1 + t3.y;
    o.z = (v3.z - mu3) * k2 + t3.z;  o.w = (v3.w - mu3) * k3 + t3.w;
    op[96] = o;
}

extern "C" void kernel_launch(void* const* d_in, const int* in_sizes, int n_in,
                              void* d_out, int out_size)
{
    const float* m      = (const float*)d_in[0];
    const float* z      = (const float*)d_in[1];
    const float* x      = (const float*)d_in[2];
    const float* ln_m_w = (const float*)d_in[3];
    const float* ln_m_b = (const float*)d_in[4];
    const float* ln_z_w = (const float*)d_in[5];
    const float* ln_z_b = (const float*)d_in[6];
    const float* lin_w  = (const float*)d_in[7];
    const float* lin_b  = (const float*)d_in[8];

    float* out_m = (float*)d_out;                      // [1024, 256]
    float* out_z = out_m + (size_t)NRES * CM;          // [1024, 1024, 128]

    // tiny prep: build g_T (8 blocks)
    re_prep_kernel<<<8, 256>>>(lin_w, lin_b, ln_z_b);

    // main: z (blocks 0..16383) + m layernorm (blocks 16384..16447)
    re_main_kernel<<<ZBLOCKS + MBLOCKS, 512>>>(
        (const float4*)z, x, (const float4*)ln_z_w, (float4*)out_z,
        (const float4*)m, (const float4*)ln_m_w, (const float4*)ln_m_b,
        (float4*)out_m);
}

// round 13
// speedup vs baseline: 1.0126x; 1.0122x over previous
#include <cuda_runtime.h>

#define NRES 1024
#define CM   256
#define CZ   128
#define EPSF 1e-5f
#define NROWS (NRES * NRES)
#define ZBLOCKS (NROWS / 64)      // 16384
#define MBLOCKS (NRES / 16)       // 64 (16 warps/block, 1 row/warp)

// Fused distogram table: T[b][c] = lin_b[c] + ln_z_b[c] + (b<15 ? lin_w[c,b] : 0)
// bin 15 == "no bin active" row (bias-only).
__device__ float g_T[16 * CZ];

__device__ __forceinline__ int dist_bin(float d2)
{
    // count of sq_bins strictly below d2 (exact fp32 boundary semantics:
    // 3.25 + 1.25k is exactly representable; squared in fp32 like the ref)
    int nb = 0;
    #pragma unroll
    for (int k = 0; k < 15; k++) {
        float bb = 3.25f + 1.25f * (float)k;
        bb = bb * bb;
        nb += (d2 > bb) ? 1 : 0;
    }
    int bin = 15;                 // no bin active -> bias-only row
    if (nb > 0) {
        if (nb == 15) {
            bin = 14;             // upper = INF
        } else {
            float bb = 3.25f + 1.25f * (float)nb;
            bb = bb * bb;
            if (d2 < bb) bin = nb - 1;   // strict: equality -> no bin
        }
    }
    return bin;
}

// ---------------------------------------------------------------------------
// Prep kernel: build g_T only (8 blocks x 256 threads).
// ---------------------------------------------------------------------------
__global__ void re_prep_kernel(
    const float* __restrict__ lin_w,
    const float* __restrict__ lin_b,
    const float* __restrict__ ln_z_b)
{
    int idx = blockIdx.x * 256 + threadIdx.x;   // 0..2047
    int b = idx >> 7;
    int c = idx & (CZ - 1);
    float v = lin_b[c] + ln_z_b[c];
    if (b < 15) v += lin_w[c * 15 + b];
    g_T[idx] = v;
}

// ---------------------------------------------------------------------------
// Main kernel.
//   blocks 0..ZBLOCKS-1          : z path, one warp per 4 consecutive rows
//   blocks ZBLOCKS..ZBLOCKS+63   : m layernorm, one warp per row of 256
// z path: bins computed warp-locally (one dist_bin chain per lane, lane&3
// selects the row) then shuffle-broadcast; all wide loads front-batched.
//   out_z = (z-mu)*rs*w[c] + T[bin][c]
// ---------------------------------------------------------------------------
__global__ __launch_bounds__(512) void re_main_kernel(
    const float4* __restrict__ z4,
    const float*  __restrict__ x,
    const float4* __restrict__ w4,      // ln_z_w as float4[32]
    float4*       __restrict__ out4,    // z output
    const float4* __restrict__ m4,
    const float4* __restrict__ mw4,     // ln_m_w
    const float4* __restrict__ mb4,     // ln_m_b
    float4*       __restrict__ outm4)   // m output
{
    int tid  = threadIdx.x;
    int lane = tid & 31;

    if (blockIdx.x >= ZBLOCKS) {
        // ---------------- m layernorm path ----------------
        int row = (blockIdx.x - ZBLOCKS) * 16 + (tid >> 5);  // 0..1023

        const float4* r = m4 + (size_t)row * 64;
        float4 a = r[lane];
        float4 c = r[lane + 32];

        float s1 = a.x + a.y + a.z + a.w + c.x + c.y + c.z + c.w;
        float s2 = a.x * a.x + a.y * a.y + a.z * a.z + a.w * a.w
                 + c.x * c.x + c.y * c.y + c.z * c.z + c.w * c.w;
        #pragma unroll
        for (int o = 16; o; o >>= 1) {
            s1 += __shfl_xor_sync(0xffffffffu, s1, o);
            s2 += __shfl_xor_sync(0xffffffffu, s2, o);
        }
        float mu  = s1 * (1.0f / CM);
        float var = s2 * (1.0f / CM) - mu * mu;
        float rs  = rsqrtf(var + EPSF);

        float4 wa = mw4[lane],      ba = mb4[lane];
        float4 wc = mw4[lane + 32], bc = mb4[lane + 32];

        float4 oa, oc;
        oa.x = (a.x - mu) * rs * wa.x + ba.x;  oa.y = (a.y - mu) * rs * wa.y + ba.y;
        oa.z = (a.z - mu) * rs * wa.z + ba.z;  oa.w = (a.w - mu) * rs * wa.w + ba.w;
        oc.x = (c.x - mu) * rs * wc.x + bc.x;  oc.y = (c.y - mu) * rs * wc.y + bc.y;
        oc.z = (c.z - mu) * rs * wc.z + bc.z;  oc.w = (c.w - mu) * rs * wc.w + bc.w;

        outm4[(size_t)row * 64 + lane]      = oa;
        outm4[(size_t)row * 64 + lane + 32] = oc;
        return;
    }

    // ---------------- z path ----------------
    int r0 = blockIdx.x * 64 + (tid >> 5) * 4;   // rows r0..r0+3, same i

    // warp-local bin computation (transient registers)
    int myrow = r0 + (lane & 3);
    int i = myrow >> 10;
    int j = myrow & (NRES - 1);
    float p0 = __ldg(&x[3 * i + 0]) - __ldg(&x[3 * j + 0]);
    float p1 = __ldg(&x[3 * i + 1]) - __ldg(&x[3 * j + 1]);
    float p2 = __ldg(&x[3 * i + 2]) - __ldg(&x[3 * j + 2]);
    int mybin = dist_bin(p0 * p0 + p1 * p1 + p2 * p2);
    int bin0 = __shfl_sync(0xffffffffu, mybin, 0);
    int bin1 = __shfl_sync(0xffffffffu, mybin, 1);
    int bin2 = __shfl_sync(0xffffffffu, mybin, 2);
    int bin3 = __shfl_sync(0xffffffffu, mybin, 3);

    // front-batch ALL wide loads
    const float4* zp = z4 + (size_t)r0 * 32 + lane;
    float4 v0 = zp[0];
    float4 v1 = zp[32];
    float4 v2 = zp[64];
    float4 v3 = zp[96];
    const float4* T4 = reinterpret_cast<const float4*>(g_T);
    float4 t0 = __ldg(T4 + bin0 * 32 + lane);   // uniform per warp, L1 hit
    float4 t1 = __ldg(T4 + bin1 * 32 + lane);
    float4 t2 = __ldg(T4 + bin2 * 32 + lane);
    float4 t3 = __ldg(T4 + bin3 * 32 + lane);
    float4 w  = __ldg(w4 + lane);               // same line all warps, L1 hit

    // interleaved one-pass moments for four rows
    float a1 = v0.x + v0.y + v0.z + v0.w;
    float a2 = v0.x * v0.x + v0.y * v0.y + v0.z * v0.z + v0.w * v0.w;
    float b1 = v1.x + v1.y + v1.z + v1.w;
    float b2 = v1.x * v1.x + v1.y * v1.y + v1.z * v1.z + v1.w * v1.w;
    float c1 = v2.x + v2.y + v2.z + v2.w;
    float c2 = v2.x * v2.x + v2.y * v2.y + v2.z * v2.z + v2.w * v2.w;
    float d1 = v3.x + v3.y + v3.z + v3.w;
    float d2 = v3.x * v3.x + v3.y * v3.y + v3.z * v3.z + v3.w * v3.w;
    #pragma unroll
    for (int o = 16; o; o >>= 1) {
        a1 += __shfl_xor_sync(0xffffffffu, a1, o);
        a2 += __shfl_xor_sync(0xffffffffu, a2, o);
        b1 += __shfl_xor_sync(0xffffffffu, b1, o);
        b2 += __shfl_xor_sync(0xffffffffu, b2, o);
        c1 += __shfl_xor_sync(0xffffffffu, c1, o);
        c2 += __shfl_xor_sync(0xffffffffu, c2, o);
        d1 += __shfl_xor_sync(0xffffffffu, d1, o);
        d2 += __shfl_xor_sync(0xffffffffu, d2, o);
    }
    float mu0 = a1 * (1.0f / CZ);
    float rs0 = rsqrtf(a2 * (1.0f / CZ) - mu0 * mu0 + EPSF);
    float mu1 = b1 * (1.0f / CZ);
    float rs1 = rsqrtf(b2 * (1.0f / CZ) - mu1 * mu1 + EPSF);
    float mu2 = c1 * (1.0f / CZ);
    float rs2 = rsqrtf(c2 * (1.0f / CZ) - mu2 * mu2 + EPSF);
    float mu3 = d1 * (1.0f / CZ);
    float rs3 = rsqrtf(d2 * (1.0f / CZ) - mu3 * mu3 + EPSF);

    float4* op = out4 + (size_t)r0 * 32 + lane;
    float4 o;
    float k0, k1, k2, k3;

    k0 = rs0 * w.x; k1 = rs0 * w.y; k2 = rs0 * w.z; k3 = rs0 * w.w;
    o.x = (v0.x - mu0) * k0 + t0.x;  o.y = (v0.y - mu0) * k1 + t0.y;
    o.z = (v0.z - mu0) * k2 + t0.z;  o.w = (v0.w - mu0) * k3 + t0.w;
    op[0] = o;

    k0 = rs1 * w.x; k1 = rs1 * w.y; k2 = rs1 * w.z; k3 = rs1 * w.w;
    o.x = (v1.x - mu1) * k0 + t1.x;  o.y = (v1.y - mu1) * k1 + t1.y;
    o.z = (v1.z - mu1) * k2 + t1.z;  o.w = (v1.w - mu1) * k3 + t1.w;
    op[32] = o;

    k0 = rs2 * w.x; k1 = rs2 * w.y; k2 = rs2 * w.z; k3 = rs2 * w.w;
    o.x = (v2.x - mu2) * k0 + t2.x;  o.y = (v2.y - mu2) * k1 + t2.y;
    o.z = (v2.z - mu2) * k2 + t2.z;  o.w = (v2.w - mu2) * k3 + t2.w;
    op[64] = o;

    k0 = rs3 * w.x; k1 = rs3 * w.y; k2 = rs3 * w.z; k3 = rs3 * w.w;
    o.x = (v3.x - mu3) * k0 + t3.x;  o.y = (v3.y - mu3) * k1 + t3.y;
    o.z = (v3.z - mu3) * k2 + t3.z;  o.w = (v3.w - mu3) * k3 + t3.w;
    op[96] = o;
}

extern "C" void kernel_launch(void* const* d_in, const int* in_sizes, int n_in,
                              void* d_out, int out_size)
{
    const float* m      = (const float*)d_in[0];
    const float* z      = (const float*)d_in[1];
    const float* x      = (const float*)d_in[2];
    const float* ln_m_w = (const float*)d_in[3];
    const float* ln_m_b = (const float*)d_in[4];
    const float* ln_z_w = (const float*)d_in[5];
    const float* ln_z_b = (const float*)d_in[6];
    const float* lin_w  = (const float*)d_in[7];
    const float* lin_b  = (const float*)d_in[8];

    float* out_m = (float*)d_out;                      // [1024, 256]
    float* out_z = out_m + (size_t)NRES * CM;          // [1024, 1024, 128]

    // tiny prep: build g_T (8 blocks)
    re_prep_kernel<<<8, 256>>>(lin_w, lin_b, ln_z_b);

    // main: z (blocks 0..16383) + m layernorm (blocks 16384..16447)
    re_main_kernel<<<ZBLOCKS + MBLOCKS, 512>>>(
        (const float4*)z, x, (const float4*)ln_z_w, (float4*)out_z,
        (const float4*)m, (const float4*)ln_m_w, (const float4*)ln_m_b,
        (float4*)out_m);
}

// round 14
// speedup vs baseline: 1.0216x; 1.0089x over previous
#include <cuda_runtime.h>

#define NRES 1024
#define CM   256
#define CZ   128
#define EPSF 1e-5f
#define NROWS (NRES * NRES)
#define ZBLOCKS (NROWS / 64)      // 16384
#define MBLOCKS (NRES / 16)       // 64 (16 warps/block, 1 row/warp)

// Fused distogram table: T[b][c] = lin_b[c] + ln_z_b[c] + (b<15 ? lin_w[c,b] : 0)
// bin 15 == "no bin active" row (bias-only).
__device__ float g_T[16 * CZ];

__device__ __forceinline__ int dist_bin(float d2)
{
    // count of sq_bins strictly below d2 (exact fp32 boundary semantics:
    // 3.25 + 1.25k is exactly representable; squared in fp32 like the ref)
    int nb = 0;
    #pragma unroll
    for (int k = 0; k < 15; k++) {
        float bb = 3.25f + 1.25f * (float)k;
        bb = bb * bb;
        nb += (d2 > bb) ? 1 : 0;
    }
    int bin = 15;                 // no bin active -> bias-only row
    if (nb > 0) {
        if (nb == 15) {
            bin = 14;             // upper = INF
        } else {
            float bb = 3.25f + 1.25f * (float)nb;
            bb = bb * bb;
            if (d2 < bb) bin = nb - 1;   // strict: equality -> no bin
        }
    }
    return bin;
}

// ---------------------------------------------------------------------------
// Prep kernel: build g_T only (8 blocks x 256 threads).
// ---------------------------------------------------------------------------
__global__ void re_prep_kernel(
    const float* __restrict__ lin_w,
    const float* __restrict__ lin_b,
    const float* __restrict__ ln_z_b)
{
    int idx = blockIdx.x * 256 + threadIdx.x;   // 0..2047
    int b = idx >> 7;
    int c = idx & (CZ - 1);
    float v = lin_b[c] + ln_z_b[c];
    if (b < 15) v += lin_w[c * 15 + b];
    g_T[idx] = v;
}

// ---------------------------------------------------------------------------
// Main kernel.
//   blocks 0..MBLOCKS-1   : m layernorm (FRONT of grid -> overlaps z stream,
//                           no tail wave), one warp per row of 256
//   blocks MBLOCKS..end   : z path, one warp per 4 consecutive rows
// z path: bins computed warp-locally (one dist_bin chain per lane, lane&3
// selects the row) then shuffle-broadcast; all wide loads front-batched.
//   out_z = (z-mu)*rs*w[c] + T[bin][c]
// ---------------------------------------------------------------------------
__global__ __launch_bounds__(512) void re_main_kernel(
    const float4* __restrict__ z4,
    const float*  __restrict__ x,
    const float4* __restrict__ w4,      // ln_z_w as float4[32]
    float4*       __restrict__ out4,    // z output
    const float4* __restrict__ m4,
    const float4* __restrict__ mw4,     // ln_m_w
    const float4* __restrict__ mb4,     // ln_m_b
    float4*       __restrict__ outm4)   // m output
{
    int tid  = threadIdx.x;
    int lane = tid & 31;

    if (blockIdx.x < MBLOCKS) {
        // ---------------- m layernorm path (wave-1 overlapped) ----------------
        int row = blockIdx.x * 16 + (tid >> 5);  // 0..1023

        const float4* r = m4 + (size_t)row * 64;
        float4 a = r[lane];
        float4 c = r[lane + 32];

        float s1 = a.x + a.y + a.z + a.w + c.x + c.y + c.z + c.w;
        float s2 = a.x * a.x + a.y * a.y + a.z * a.z + a.w * a.w
                 + c.x * c.x + c.y * c.y + c.z * c.z + c.w * c.w;
        #pragma unroll
        for (int o = 16; o; o >>= 1) {
            s1 += __shfl_xor_sync(0xffffffffu, s1, o);
            s2 += __shfl_xor_sync(0xffffffffu, s2, o);
        }
        float mu  = s1 * (1.0f / CM);
        float var = s2 * (1.0f / CM) - mu * mu;
        float rs  = rsqrtf(var + EPSF);

        float4 wa = mw4[lane],      ba = mb4[lane];
        float4 wc = mw4[lane + 32], bc = mb4[lane + 32];

        float4 oa, oc;
        oa.x = (a.x - mu) * rs * wa.x + ba.x;  oa.y = (a.y - mu) * rs * wa.y + ba.y;
        oa.z = (a.z - mu) * rs * wa.z + ba.z;  oa.w = (a.w - mu) * rs * wa.w + ba.w;
        oc.x = (c.x - mu) * rs * wc.x + bc.x;  oc.y = (c.y - mu) * rs * wc.y + bc.y;
        oc.z = (c.z - mu) * rs * wc.z + bc.z;  oc.w = (c.w - mu) * rs * wc.w + bc.w;

        outm4[(size_t)row * 64 + lane]      = oa;
        outm4[(size_t)row * 64 + lane + 32] = oc;
        return;
    }

    // ---------------- z path ----------------
    int r0 = (blockIdx.x - MBLOCKS) * 64 + (tid >> 5) * 4;   // rows r0..r0+3, same i

    // warp-local bin computation (transient registers)
    int myrow = r0 + (lane & 3);
    int i = myrow >> 10;
    int j = myrow & (NRES - 1);
    float p0 = __ldg(&x[3 * i + 0]) - __ldg(&x[3 * j + 0]);
    float p1 = __ldg(&x[3 * i + 1]) - __ldg(&x[3 * j + 1]);
    float p2 = __ldg(&x[3 * i + 2]) - __ldg(&x[3 * j + 2]);
    int mybin = dist_bin(p0 * p0 + p1 * p1 + p2 * p2);
    int bin0 = __shfl_sync(0xffffffffu, mybin, 0);
    int bin1 = __shfl_sync(0xffffffffu, mybin, 1);
    int bin2 = __shfl_sync(0xffffffffu, mybin, 2);
    int bin3 = __shfl_sync(0xffffffffu, mybin, 3);

    // front-batch ALL wide loads
    const float4* zp = z4 + (size_t)r0 * 32 + lane;
    float4 v0 = zp[0];
    float4 v1 = zp[32];
    float4 v2 = zp[64];
    float4 v3 = zp[96];
    const float4* T4 = reinterpret_cast<const float4*>(g_T);
    float4 t0 = __ldg(T4 + bin0 * 32 + lane);   // uniform per warp, L1 hit
    float4 t1 = __ldg(T4 + bin1 * 32 + lane);
    float4 t2 = __ldg(T4 + bin2 * 32 + lane);
    float4 t3 = __ldg(T4 + bin3 * 32 + lane);
    float4 w  = __ldg(w4 + lane);               // same line all warps, L1 hit

    // interleaved one-pass moments for four rows
    float a1 = v0.x + v0.y + v0.z + v0.w;
    float a2 = v0.x * v0.x + v0.y * v0.y + v0.z * v0.z + v0.w * v0.w;
    float b1 = v1.x + v1.y + v1.z + v1.w;
    float b2 = v1.x * v1.x + v1.y * v1.y + v1.z * v1.z + v1.w * v1.w;
    float c1 = v2.x + v2.y + v2.z + v2.w;
    float c2 = v2.x * v2.x + v2.y * v2.y + v2.z * v2.z + v2.w * v2.w;
    float d1 = v3.x + v3.y + v3.z + v3.w;
    float d2 = v3.x * v3.x + v3.y * v3.y + v3.z * v3.z + v3.w * v3.w;
    #pragma unroll
    for (int o = 16; o; o >>= 1) {
        a1 += __shfl_xor_sync(0xffffffffu, a1, o);
        a2 += __shfl_xor_sync(0xffffffffu, a2, o);
        b1 += __shfl_xor_sync(0xffffffffu, b1, o);
        b2 += __shfl_xor_sync(0xffffffffu, b2, o);
        c1 += __shfl_xor_sync(0xffffffffu, c1, o);
        c2 += __shfl_xor_sync(0xffffffffu, c2, o);
        d1 += __shfl_xor_sync(0xffffffffu, d1, o);
        d2 += __shfl_xor_sync(0xffffffffu, d2, o);
    }
    float mu0 = a1 * (1.0f / CZ);
    float rs0 = rsqrtf(a2 * (1.0f / CZ) - mu0 * mu0 + EPSF);
    float mu1 = b1 * (1.0f / CZ);
    float rs1 = rsqrtf(b2 * (1.0f / CZ) - mu1 * mu1 + EPSF);
    float mu2 = c1 * (1.0f / CZ);
    float rs2 = rsqrtf(c2 * (1.0f / CZ) - mu2 * mu2 + EPSF);
    float mu3 = d1 * (1.0f / CZ);
    float rs3 = rsqrtf(d2 * (1.0f / CZ) - mu3 * mu3 + EPSF);

    float4* op = out4 + (size_t)r0 * 32 + lane;
    float4 o;
    float k0, k1, k2, k3;

    k0 = rs0 * w.x; k1 = rs0 * w.y; k2 = rs0 * w.z; k3 = rs0 * w.w;
    o.x = (v0.x - mu0) * k0 + t0.x;  o.y = (v0.y - mu0) * k1 + t0.y;
    o.z = (v0.z - mu0) * k2 + t0.z;  o.w = (v0.w - mu0) * k3 + t0.w;
    op[0] = o;

    k0 = rs1 * w.x; k1 = rs1 * w.y; k2 = rs1 * w.z; k3 = rs1 * w.w;
    o.x = (v1.x - mu1) * k0 + t1.x;  o.y = (v1.y - mu1) * k1 + t1.y;
    o.z = (v1.z - mu1) * k2 + t1.z;  o.w = (v1.w - mu1) * k3 + t1.w;
    op[32] = o;

    k0 = rs2 * w.x; k1 = rs2 * w.y; k2 = rs2 * w.z; k3 = rs2 * w.w;
    o.x = (v2.x - mu2) * k0 + t2.x;  o.y = (v2.y - mu2) * k1 + t2.y;
    o.z = (v2.z - mu2) * k2 + t2.z;  o.w = (v2.w - mu2) * k3 + t2.w;
    op[64] = o;

    k0 = rs3 * w.x; k1 = rs3 * w.y; k2 = rs3 * w.z; k3 = rs3 * w.w;
    o.x = (v3.x - mu3) * k0 + t3.x;  o.y = (v3.y - mu3) * k1 + t3.y;
    o.z = (v3.z - mu3) * k2 + t3.z;  o.w = (v3.w - mu3) * k3 + t3.w;
    op[96] = o;
}

extern "C" void kernel_launch(void* const* d_in, const int* in_sizes, int n_in,
                              void* d_out, int out_size)
{
    const float* m      = (const float*)d_in[0];
    const float* z      = (const float*)d_in[1];
    const float* x      = (const float*)d_in[2];
    const float* ln_m_w = (const float*)d_in[3];
    const float* ln_m_b = (const float*)d_in[4];
    const float* ln_z_w = (const float*)d_in[5];
    const float* ln_z_b = (const float*)d_in[6];
    const float* lin_w  = (const float*)d_in[7];
    const float* lin_b  = (const float*)d_in[8];

    float* out_m = (float*)d_out;                      // [1024, 256]
    float* out_z = out_m + (size_t)NRES * CM;          // [1024, 1024, 128]

    // tiny prep: build g_T (8 blocks)
    re_prep_kernel<<<8, 256>>>(lin_w, lin_b, ln_z_b);

    // main: m layernorm (blocks 0..63, overlapped) + z (blocks 64..16447)
    re_main_kernel<<<MBLOCKS + ZBLOCKS, 512>>>(
        (const float4*)z, x, (const float4*)ln_z_w, (float4*)out_z,
        (const float4*)m, (const float4*)ln_m_w, (const float4*)ln_m_b,
        (float4*)out_m);
}

// round 17
// speedup vs baseline: 1.0278x; 1.0061x over previous
#include <cuda_runtime.h>

#define NRES 1024
#define CM   256
#define CZ   128
#define EPSF 1e-5f
#define NROWS (NRES * NRES)
#define ZBLOCKS (NROWS / 64)      // 16384
#define TBLOCKS 4                 // g_T build blocks (512 threads each)
#define MBLOCKS (NRES / 16)       // 64 m-layernorm blocks

// Fused distogram table: T[b][c] = lin_b[c] + ln_z_b[c] + (b<15 ? lin_w[c,b] : 0)
// bin 15 == "no bin active" row (bias-only).
__device__ float g_T[16 * CZ];

__device__ __forceinline__ int dist_bin(float d2)
{
    // count of sq_bins strictly below d2 (exact fp32 boundary semantics:
    // 3.25 + 1.25k is exactly representable; squared in fp32 like the ref)
    int nb = 0;
    #pragma unroll
    for (int k = 0; k < 15; k++) {
        float bb = 3.25f + 1.25f * (float)k;
        bb = bb * bb;
        nb += (d2 > bb) ? 1 : 0;
    }
    int bin = 15;                 // no bin active -> bias-only row
    if (nb > 0) {
        if (nb == 15) {
            bin = 14;             // upper = INF
        } else {
            float bb = 3.25f + 1.25f * (float)nb;
            bb = bb * bb;
            if (d2 < bb) bin = nb - 1;   // strict: equality -> no bin
        }
    }
    return bin;
}

// ---------------------------------------------------------------------------
// Prep kernel (primary in the PDL pair).
//   blocks 0..3   : build g_T (2048 floats), then trigger PDL completion
//   blocks 4..67  : trigger immediately, then m layernorm (no g_T dependency)
// ---------------------------------------------------------------------------
__global__ __launch_bounds__(512) void re_prep_kernel(
    const float*  __restrict__ lin_w,
    const float*  __restrict__ lin_b,
    const float*  __restrict__ ln_z_b,
    const float4* __restrict__ m4,
    const float4* __restrict__ mw4,
    const float4* __restrict__ mb4,
    float4*       __restrict__ outm4)
{
    int tid = threadIdx.x;
    if (blockIdx.x < TBLOCKS) {
        int idx = blockIdx.x * 512 + tid;   // 0..2047
        int b = idx >> 7;
        int c = idx & (CZ - 1);
        float v = lin_b[c] + ln_z_b[c];
        if (b < 15) v += lin_w[c * 15 + b];
        g_T[idx] = v;
        cudaTriggerProgrammaticLaunchCompletion();
        return;
    }
    cudaTriggerProgrammaticLaunchCompletion();

    // ---------------- m layernorm ----------------
    int lane = tid & 31;
    int row  = (blockIdx.x - TBLOCKS) * 16 + (tid >> 5);  // 0..1023

    const float4* r = m4 + (size_t)row * 64;
    float4 a = r[lane];
    float4 c = r[lane + 32];

    float s1 = a.x + a.y + a.z + a.w + c.x + c.y + c.z + c.w;
    float s2 = a.x * a.x + a.y * a.y + a.z * a.z + a.w * a.w
             + c.x * c.x + c.y * c.y + c.z * c.z + c.w * c.w;
    #pragma unroll
    for (int o = 16; o; o >>= 1) {
        s1 += __shfl_xor_sync(0xffffffffu, s1, o);
        s2 += __shfl_xor_sync(0xffffffffu, s2, o);
    }
    float mu  = s1 * (1.0f / CM);
    float var = s2 * (1.0f / CM) - mu * mu;
    float rs  = rsqrtf(var + EPSF);

    float4 wa = mw4[lane],      ba = mb4[lane];
    float4 wc = mw4[lane + 32], bc = mb4[lane + 32];

    float4 oa, oc;
    oa.x = (a.x - mu) * rs * wa.x + ba.x;  oa.y = (a.y - mu) * rs * wa.y + ba.y;
    oa.z = (a.z - mu) * rs * wa.z + ba.z;  oa.w = (a.w - mu) * rs * wa.w + ba.w;
    oc.x = (c.x - mu) * rs * wc.x + bc.x;  oc.y = (c.y - mu) * rs * wc.y + bc.y;
    oc.z = (c.z - mu) * rs * wc.z + bc.z;  oc.w = (c.w - mu) * rs * wc.w + bc.w;

    outm4[(size_t)row * 64 + lane]      = oa;
    outm4[(size_t)row * 64 + lane + 32] = oc;
}

// ---------------------------------------------------------------------------
// z kernel (secondary in the PDL pair): one warp per FOUR consecutive rows.
// Bins warp-locally (one dist_bin chain per lane, lane&3 selects the row),
// shuffle-broadcast; big z loads issued BEFORE the grid-dependency sync so
// they overlap the prep kernel; T loads (g_T-dependent) after the sync.
//   out_z = (z-mu)*rs*w[c] + T[bin][c]
// ---------------------------------------------------------------------------
__global__ __launch_bounds__(512) void re_z_kernel(
    const float4* __restrict__ z4,
    const float*  __restrict__ x,
    const float4* __restrict__ w4,      // ln_z_w as float4[32]
    float4*       __restrict__ out4)
{
    int tid  = threadIdx.x;
    int lane = tid & 31;
    int r0   = blockIdx.x * 64 + (tid >> 5) * 4;   // rows r0..r0+3, same i

    // warp-local bin computation (transient registers, no g_T dependency)
    int myrow = r0 + (lane & 3);
    int i = myrow >> 10;
    int j = myrow & (NRES - 1);
    float p0 = __ldg(&x[3 * i + 0]) - __ldg(&x[3 * j + 0]);
    float p1 = __ldg(&x[3 * i + 1]) - __ldg(&x[3 * j + 1]);
    float p2 = __ldg(&x[3 * i + 2]) - __ldg(&x[3 * j + 2]);
    int mybin = dist_bin(p0 * p0 + p1 * p1 + p2 * p2);
    int bin0 = __shfl_sync(0xffffffffu, mybin, 0);
    int bin1 = __shfl_sync(0xffffffffu, mybin, 1);
    int bin2 = __shfl_sync(0xffffffffu, mybin, 2);
    int bin3 = __shfl_sync(0xffffffffu, mybin, 3);

    // big streaming loads — issued before the PDL sync, overlap prep kernel
    const float4* zp = z4 + (size_t)r0 * 32 + lane;
    float4 v0 = zp[0];
    float4 v1 = zp[32];
    float4 v2 = zp[64];
    float4 v3 = zp[96];

    // wait for prep's g_T writes to be visible, then load T rows + w
    cudaGridDependencySynchronize();

    const float4* T4 = reinterpret_cast<const float4*>(g_T);
    float4 t0 = __ldg(T4 + bin0 * 32 + lane);   // uniform per warp, L1 hit
    float4 t1 = __ldg(T4 + bin1 * 32 + lane);
    float4 t2 = __ldg(T4 + bin2 * 32 + lane);
    float4 t3 = __ldg(T4 + bin3 * 32 + lane);
    float4 w  = __ldg(w4 + lane);               // same line all warps, L1 hit

    // interleaved one-pass moments for four rows
    float a1 = v0.x + v0.y + v0.z + v0.w;
    float a2 = v0.x * v0.x + v0.y * v0.y + v0.z * v0.z + v0.w * v0.w;
    float b1 = v1.x + v1.y + v1.z + v1.w;
    float b2 = v1.x * v1.x + v1.y * v1.y + v1.z * v1.z + v1.w * v1.w;
    float c1 = v2.x + v2.y + v2.z + v2.w;
    float c2 = v2.x * v2.x + v2.y * v2.y + v2.z * v2.z + v2.w * v2.w;
    float d1 = v3.x + v3.y + v3.z + v3.w;
    float d2 = v3.x * v3.x + v3.y * v3.y + v3.z * v3.z + v3.w * v3.w;
    #pragma unroll
    for (int o = 16; o; o >>= 1) {
        a1 += __shfl_xor_sync(0xffffffffu, a1, o);
        a2 += __shfl_xor_sync(0xffffffffu, a2, o);
        b1 += __shfl_xor_sync(0xffffffffu, b1, o);
        b2 += __shfl_xor_sync(0xffffffffu, b2, o);
        c1 += __shfl_xor_sync(0xffffffffu, c1, o);
        c2 += __shfl_xor_sync(0xffffffffu, c2, o);
        d1 += __shfl_xor_sync(0xffffffffu, d1, o);
        d2 += __shfl_xor_sync(0xffffffffu, d2, o);
    }
    float mu0 = a1 * (1.0f / CZ);
    float rs0 = rsqrtf(a2 * (1.0f / CZ) - mu0 * mu0 + EPSF);
    float mu1 = b1 * (1.0f / CZ);
    float rs1 = rsqrtf(b2 * (1.0f / CZ) - mu1 * mu1 + EPSF);
    float mu2 = c1 * (1.0f / CZ);
    float rs2 = rsqrtf(c2 * (1.0f / CZ) - mu2 * mu2 + EPSF);
    float mu3 = d1 * (1.0f / CZ);
    float rs3 = rsqrtf(d2 * (1.0f / CZ) - mu3 * mu3 + EPSF);

    float4* op = out4 + (size_t)r0 * 32 + lane;
    float4 o;
    float k0, k1, k2, k3;

    k0 = rs0 * w.x; k1 = rs0 * w.y; k2 = rs0 * w.z; k3 = rs0 * w.w;
    o.x = (v0.x - mu0) * k0 + t0.x;  o.y = (v0.y - mu0) * k1 + t0.y;
    o.z = (v0.z - mu0) * k2 + t0.z;  o.w = (v0.w - mu0) * k3 + t0.w;
    op[0] = o;

    k0 = rs1 * w.x; k1 = rs1 * w.y; k2 = rs1 * w.z; k3 = rs1 * w.w;
    o.x = (v1.x - mu1) * k0 + t1.x;  o.y = (v1.y - mu1) * k1 + t1.y;
    o.z = (v1.z - mu1) * k2 + t1.z;  o.w = (v1.w - mu1) * k3 + t1.w;
    op[32] = o;

    k0 = rs2 * w.x; k1 = rs2 * w.y; k2 = rs2 * w.z; k3 = rs2 * w.w;
    o.x = (v2.x - mu2) * k0 + t2.x;  o.y = (v2.y - mu2) * k1 + t2.y;
    o.z = (v2.z - mu2) * k2 + t2.z;  o.w = (v2.w - mu2) * k3 + t2.w;
    op[64] = o;

    k0 = rs3 * w.x; k1 = rs3 * w.y; k2 = rs3 * w.z; k3 = rs3 * w.w;
    o.x = (v3.x - mu3) * k0 + t3.x;  o.y = (v3.y - mu3) * k1 + t3.y;
    o.z = (v3.z - mu3) * k2 + t3.z;  o.w = (v3.w - mu3) * k3 + t3.w;
    op[96] = o;
}

extern "C" void kernel_launch(void* const* d_in, const int* in_sizes, int n_in,
                              void* d_out, int out_size)
{
    const float* m      = (const float*)d_in[0];
    const float* z      = (const float*)d_in[1];
    const float* x      = (const float*)d_in[2];
    const float* ln_m_w = (const float*)d_in[3];
    const float* ln_m_b = (const float*)d_in[4];
    const float* ln_z_w = (const float*)d_in[5];
    const float* ln_z_b = (const float*)d_in[6];
    const float* lin_w  = (const float*)d_in[7];
    const float* lin_b  = (const float*)d_in[8];

    float* out_m = (float*)d_out;                      // [1024, 256]
    float* out_z = out_m + (size_t)NRES * CM;          // [1024, 1024, 128]

    // primary: g_T build (blocks 0..3, triggers PDL) + m layernorm (4..67)
    re_prep_kernel<<<TBLOCKS + MBLOCKS, 512>>>(
        lin_w, lin_b, ln_z_b,
        (const float4*)m, (const float4*)ln_m_w, (const float4*)ln_m_b,
        (float4*)out_m);

    // secondary: pure z, launched with programmatic dependent launch so it
    // overlaps the prep kernel; g_T reads are guarded by griddepsync.
    cudaLaunchConfig_t cfg = {};
    cfg.gridDim  = dim3(ZBLOCKS);
    cfg.blockDim = dim3(512);
    cfg.dynamicSmemBytes = 0;
    cfg.stream = 0;
    cudaLaunchAttribute attr[1];
    attr[0].id = cudaLaunchAttributeProgrammaticStreamSerialization;
    attr[0].val.programmaticStreamSerializationAllowed = 1;
    cfg.attrs = attr;
    cfg.numAttrs = 1;
    cudaLaunchKernelEx(&cfg, re_z_kernel,
                       (const float4*)z, x, (const float4*)ln_z_w,
                       (float4*)out_z);
}